// round 16
// baseline (speedup 1.0000x reference)
#include <cuda_runtime.h>
#include <cuda_bf16.h>
#include <math.h>

// Problem constants
#define B_   16
#define L_   256
#define LQ_  64
#define ET_  128
#define H_   4
#define ETK_ 32
#define DIM_ 64
#define D_IN_ 32
#define IE_  8

typedef unsigned long long ull;

// ---------------- scratch (device globals; no allocation) ----------------
__device__ float g_q[H_ * LQ_ * ETK_];   // (h, q, e)  pre-scaled by 1/sqrt(32)
__device__ float g_k[B_ * H_ * L_ * ETK_];
__device__ float g_Wc[ET_ * ET_];        // 128x128 compact Wo @ W_ih
__device__ float g_bc[ET_];
__device__ float g_pre[B_ * LQ_ * ET_];  // accumulated by attn (atomics); zeroed by rnn

__device__ __forceinline__ void ffma2(ull& acc, ull a, ull b)
{
    asm("fma.rn.f32x2 %0, %1, %2, %0;" : "+l"(acc) : "l"(a), "l"(b));
}
__device__ __forceinline__ ull fadd2(ull a, ull b)
{
    ull r; asm("add.rn.f32x2 %0, %1, %2;" : "=l"(r) : "l"(a), "l"(b)); return r;
}
__device__ __forceinline__ float2 unpack2(ull a)
{
    float2 v; asm("mov.b64 {%0,%1}, %2;" : "=f"(v.x), "=f"(v.y) : "l"(a)); return v;
}
__device__ __forceinline__ ull bcast2(float v)
{
    ull r; asm("mov.b64 %0, {%1,%1};" : "=l"(r) : "f"(v)); return r;
}
__device__ __forceinline__ float tanh_fast(float x)
{
    float r; asm("tanh.approx.f32 %0, %1;" : "=f"(r) : "f"(x)); return r;
}
__device__ __forceinline__ void cp_async16(float* dst_smem, const float4* src)
{
    unsigned d = (unsigned)__cvta_generic_to_shared(dst_smem);
    asm volatile("cp.async.cg.shared.global [%0], [%1], 16;" :: "r"(d), "l"(src));
}

// ======================================================================
// Kernel 1: 256 threads/block, 16 rows/block, f32x2 GEMM with 8
// accumulators (even/odd k sets -> half the RAW chain), transposed
// stride-18 s_a, cp.async double-buffered 32-row W chunks. 5 blk/SM.
//   blocks 0..255: K rows  256..259: Q  260..267: Wc  268: bias
// ======================================================================
#define SA_STR 18
#define CHUNK_ROWS 32
#define NCHUNK 4

__global__ void __launch_bounds__(256, 5)
stage1_kernel(
    const float* __restrict__ times, const float* __restrict__ query,
    const float* __restrict__ w_lin, const float* __restrict__ b_lin,
    const float* __restrict__ w_per, const float* __restrict__ b_per,
    const float* __restrict__ Wk, const float* __restrict__ bk,
    const float* __restrict__ Wq, const float* __restrict__ bq,
    const float* __restrict__ Wo, const float* __restrict__ bo,
    const float* __restrict__ W_ih, const float* __restrict__ b_ih,
    const float* __restrict__ b_hh)
{
    extern __shared__ float sm[];
    float* s_a = sm;                             // transposed [c][r], stride 18
    float* s_w0 = sm + 128 * SA_STR;             // 32 x 128 chunk buf 0
    float* s_w1 = s_w0 + CHUNK_ROWS * 128;       // 32 x 128 chunk buf 1
    __shared__ float tv[16];

    const int tid = threadIdx.x;
    const int bx  = blockIdx.x;
    const int tx = tid & 31;      // col group: cols 4*tx..4*tx+3
    const int ty = tid >> 5;      // row group: rows 2*ty, 2*ty+1

    if (bx < 268) {
        const bool is_wc = (bx >= 260);
        const bool is_q  = (!is_wc) && (bx >= 256);
        const float* W = is_wc ? W_ih : (is_q ? Wq : Wk);

        // prefetch chunk 0 immediately (overlaps s_a fill)
        {
            float* dst = s_w0;
#pragma unroll
            for (int i = 0; i < 4; i++)
                cp_async16(dst + 4 * (tid + 256 * i),
                           (const float4*)W + tid + 256 * i);
            asm volatile("cp.async.commit_group;");
        }

        // ---- fill s_a (transposed) ----
        if (!is_wc) {
            const int r0 = bx * 16;
            if (tid < 16) tv[tid] = is_q ? query[r0 - 4096 + tid] : times[r0 + tid];
            __syncthreads();
            const float wl = w_lin[0], bl = b_lin[0];
            for (int idx = tid; idx < 16 * 128; idx += 256) {
                int r = idx & 15, c = idx >> 4;
                float t = tv[r];
                s_a[c * SA_STR + r] =
                    (c == 0) ? fmaf(t, wl, bl)
                             : __sinf(fmaf(t, w_per[c - 1], b_per[c - 1]));
            }
        } else {
            const int cr0 = (bx - 260) * 16;
            for (int idx = tid; idx < 16 * 128; idx += 256) {
                int rr = idx & 15, c = idx >> 4;
                int cr = cr0 + rr;
                int r = (cr >> 5) * 64 + (cr & 31);   // d<32 rows of Wo
                s_a[c * SA_STR + rr] = Wo[r * 128 + c];
            }
        }

        // ---- f32x2 GEMM over 4 k-chunks; 8 accumulators (2 sets) ----
        ull a01[2][2] = {{0, 0}, {0, 0}};   // [set][row]
        ull a23[2][2] = {{0, 0}, {0, 0}};
#pragma unroll
        for (int ch = 0; ch < NCHUNK; ch++) {
            float* buf_cur = (ch & 1) ? s_w1 : s_w0;
            if (ch + 1 < NCHUNK) {
                float* buf_nxt = (ch & 1) ? s_w0 : s_w1;
                const float4* src = (const float4*)(W + (ch + 1) * CHUNK_ROWS * 128);
#pragma unroll
                for (int i = 0; i < 4; i++)
                    cp_async16(buf_nxt + 4 * (tid + 256 * i), src + tid + 256 * i);
                asm volatile("cp.async.commit_group;");
                asm volatile("cp.async.wait_group 1;" ::: "memory");
            } else {
                asm volatile("cp.async.wait_group 0;" ::: "memory");
            }
            __syncthreads();

#pragma unroll 4
            for (int i = 0; i < CHUNK_ROWS; i += 2) {
#pragma unroll
                for (int s = 0; s < 2; s++) {
                    ulonglong2 wv = *(const ulonglong2*)(buf_cur + (i + s) * 128 + 4 * tx);
                    float2 av = *(const float2*)(s_a + (ch * CHUNK_ROWS + i + s) * SA_STR + 2 * ty);
                    ull e0 = bcast2(av.x), e1 = bcast2(av.y);
                    ffma2(a01[s][0], e0, wv.x); ffma2(a23[s][0], e0, wv.y);
                    ffma2(a01[s][1], e1, wv.x); ffma2(a23[s][1], e1, wv.y);
                }
            }
            __syncthreads();   // all reads of buf_cur done before its overwrite
        }
        ull acc01[2], acc23[2];
#pragma unroll
        for (int r = 0; r < 2; r++) {
            acc01[r] = fadd2(a01[0][r], a01[1][r]);
            acc23[r] = fadd2(a23[0][r], a23[1][r]);
        }

        // ---- epilogue ----
        if (!is_wc) {
            const int r0 = bx * 16;
            const float* bias = is_q ? bq : bk;
            const float scale = is_q ? 0.17677669529663687f : 1.0f;
#pragma unroll
            for (int r = 0; r < 2; r++) {
                int grow = r0 + 2 * ty + r;
                float2 p01 = unpack2(acc01[r]);
                float2 p23 = unpack2(acc23[r]);
                float vr[4] = {p01.x, p01.y, p23.x, p23.y};
#pragma unroll
                for (int c = 0; c < 4; c++) {
                    int col = 4 * tx + c;
                    float v = (vr[c] + bias[col]) * scale;
                    int h = col >> 5, e = col & 31;
                    if (is_q) g_q[(h * LQ_ + (grow - 4096)) * ETK_ + e] = v;
                    else {
                        int b = grow >> 8, l = grow & 255;
                        g_k[((b * H_ + h) * L_ + l) * ETK_ + e] = v;
                    }
                }
            }
        } else {
            const int cr0 = (bx - 260) * 16;
#pragma unroll
            for (int r = 0; r < 2; r++) {
                float2 p01 = unpack2(acc01[r]);
                float2 p23 = unpack2(acc23[r]);
                int row = cr0 + 2 * ty + r;
                g_Wc[row * 128 + 4 * tx]     = p01.x;
                g_Wc[row * 128 + 4 * tx + 1] = p01.y;
                g_Wc[row * 128 + 4 * tx + 2] = p23.x;
                g_Wc[row * 128 + 4 * tx + 3] = p23.y;
            }
        }
    } else {
        // bias: bc = (bo + sum_ones Wo[r]) @ W_ih + b_ih + b_hh
        const int j = tid & 127, hf = tid >> 7;
        float accv = 0.f;
#pragma unroll 4
        for (int i = 0; i < 64; i++) {
            int oi = hf * 64 + i;
            int r = (oi >> 5) * 64 + 32 + (oi & 31);  // "ones" rows of Wo
            accv += Wo[r * 128 + j];
        }
        s_a[256 + hf * 128 + j] = accv;
        __syncthreads();
        if (tid < 128) s_a[tid] = bo[tid] + s_a[256 + tid] + s_a[384 + tid];

        float acc = (tid < 128) ? (b_ih[tid] + b_hh[tid]) : 0.f;
#pragma unroll
        for (int ch = 0; ch < 2; ch++) {
            __syncthreads();
#pragma unroll
            for (int idx = tid * 4; idx < 64 * 128; idx += 1024)
                *(float4*)(s_w0 + idx) = *(const float4*)(W_ih + ch * 64 * 128 + idx);
            __syncthreads();
            if (tid < 128) {
#pragma unroll 8
                for (int i = 0; i < 64; i++)
                    acc = fmaf(s_a[ch * 64 + i], s_w0[i * 128 + tid], acc);
            }
        }
        if (tid < 128) g_bc[tid] = acc;
    }
}

// ======================================================================
// Kernel 2: masked attention + fused partial-pre accumulation.
// grid (qt=4, h=4, b=16), 256 threads, smem 51200 B -> 4 blocks/SM.
// num/den uses 8 accumulators (even/odd k) to halve the RAW chain.
// ======================================================================
__global__ void __launch_bounds__(256, 4)
attn_kernel(const float* __restrict__ x, const float* __restrict__ mask)
{
    extern __shared__ float smem[];
    float*  qv  = smem;                          // 512 (reused as att_s later)
    float*  s_s = smem + 512;                    // 16*256
    float2* mxm = (float2*)(smem + 512 + 4096);  // 128*32 float2 (32KB chunk)

    const int tid = threadIdx.x;
    const int qt = blockIdx.x, h = blockIdx.y, b = blockIdx.z;

    qv[tid]       = g_q[(h * LQ_ + qt * 16) * ETK_ + tid];
    qv[tid + 256] = g_q[(h * LQ_ + qt * 16) * ETK_ + tid + 256];
    __syncthreads();

    // scores: thread = key k, all 16 queries
    {
        const int k = tid;
        const float* kp = g_k + ((b * H_ + h) * L_ + k) * ETK_;
        float kv[32];
#pragma unroll
        for (int i = 0; i < 8; i++) {
            float4 v = *(const float4*)(kp + 4 * i);
            kv[4*i] = v.x; kv[4*i+1] = v.y; kv[4*i+2] = v.z; kv[4*i+3] = v.w;
        }
#pragma unroll
        for (int q = 0; q < 16; q++) {
            float acc = 0.f;
#pragma unroll
            for (int e = 0; e < 32; e++) acc = fmaf(qv[q * 32 + e], kv[e], acc);
            s_s[q * 256 + k] = acc;
        }
    }
    __syncthreads();

    // row max + exp (8 warps x 2 queries)
    {
        const int wq = tid >> 5, lane = tid & 31;
#pragma unroll
        for (int qq = 0; qq < 2; qq++) {
            int q = wq * 2 + qq;
            float vals[8], m = -1e30f;
#pragma unroll
            for (int i = 0; i < 8; i++) {
                vals[i] = s_s[q * 256 + lane + 32 * i];
                m = fmaxf(m, vals[i]);
            }
#pragma unroll
            for (int off = 16; off; off >>= 1)
                m = fmaxf(m, __shfl_xor_sync(0xffffffffu, m, off));
#pragma unroll
            for (int i = 0; i < 8; i++)
                s_s[q * 256 + lane + 32 * i] = __expf(vals[i] - m);
        }
    }

    // num/den over 2 key-chunks; 8 accumulators (even/odd k)
    const int q  = tid >> 4;
    const int d0 = (tid & 15) * 2;
    float n0a = 0.f, de0a = 0.f, n1a = 0.f, de1a = 0.f;
    float n0b = 0.f, de0b = 0.f, n1b = 0.f, de1b = 0.f;
#pragma unroll
    for (int ch = 0; ch < 2; ch++) {
        __syncthreads();   // protect mxm reuse
        const float* xb = x    + (b * L_ + ch * 128) * D_IN_;
        const float* mb = mask + (b * L_ + ch * 128) * D_IN_;
        for (int idx = tid; idx < 128 * D_IN_; idx += 256) {
            float m = mb[idx];
            mxm[idx] = make_float2(m * xb[idx], m);
        }
        __syncthreads();

        const float* ep = s_s + q * 256 + ch * 128;
#pragma unroll 4
        for (int k = 0; k < 128; k += 2) {
            float ea = ep[k];
            float4 va = *(const float4*)(mxm + k * 32 + d0);
            n0a = fmaf(ea, va.x, n0a); de0a = fmaf(ea, va.y, de0a);
            n1a = fmaf(ea, va.z, n1a); de1a = fmaf(ea, va.w, de1a);
            float eb = ep[k + 1];
            float4 vb = *(const float4*)(mxm + (k + 1) * 32 + d0);
            n0b = fmaf(eb, vb.x, n0b); de0b = fmaf(eb, vb.y, de0b);
            n1b = fmaf(eb, vb.z, n1b); de1b = fmaf(eb, vb.w, de1b);
        }
    }
    float n0 = n0a + n0b, de0 = de0a + de0b;
    float n1 = n1a + n1b, de1 = de1a + de1b;
    __syncthreads();
    qv[q * 32 + d0]     = (de0 > 0.f) ? (n0 / de0) : 0.f;   // att_s
    qv[q * 32 + d0 + 1] = (de1 > 0.f) ? (n1 / de1) : 0.f;
    __syncthreads();

    // partial pre: pre[b, q, col] += sum_d att[q,d] * Wc[h*32+d, col]
    {
        const int col = tid & 127;
        const int rh  = (tid >> 7) * 8;    // rows rh..rh+7
        const float* wp = g_Wc + (h * 32) * 128 + col;
        float a[8];
#pragma unroll
        for (int r = 0; r < 8; r++) a[r] = 0.f;
#pragma unroll 4
        for (int d = 0; d < 32; d++) {
            float w = wp[d * 128];
#pragma unroll
            for (int r = 0; r < 8; r++)
                a[r] = fmaf(qv[(rh + r) * 32 + d], w, a[r]);
        }
        float bias = (h == 0) ? g_bc[col] : 0.f;
        float* pp = g_pre + (b * LQ_ + qt * 16 + rh) * 128 + col;
#pragma unroll
        for (int r = 0; r < 8; r++)
            atomicAdd(pp + r * 128, a[r] + bias);
    }
}

// ======================================================================
// Kernel 3: RNN + regressor. grid 16 x 128 threads. Regressor matvecs
// use 4 accumulators (chain 512 -> 128 cyc per layer).
// ======================================================================
__global__ void __launch_bounds__(128, 1)
rnn_regr_kernel(const float* __restrict__ W_hh,
                const float* __restrict__ r1_w, const float* __restrict__ r1_b,
                const float* __restrict__ r2_w, const float* __restrict__ r2_b,
                const float* __restrict__ r3_w, const float* __restrict__ r3_b,
                const float* __restrict__ r4_w, const float* __restrict__ r4_b,
                float* __restrict__ out)
{
    extern __shared__ float smem[];
    float* A     = smem;             // 16384 floats: pre slab (8192) then r3_w
    float* r1_s  = smem + 16384;     // 16384
    float* r2_s  = r1_s + 16384;     // 16384
    float* h2    = r2_s + 16384;     // 256
    float* v_s   = h2 + 256;         // 128
    float* partf = v_s + 128;        // 32
    float* pre_s = A;

    const int tid = threadIdx.x;

    // Stage pre slab and zero g_pre for next replay
    {
        float4* src = (float4*)(g_pre + blockIdx.x * LQ_ * ET_);
        float4* dst = (float4*)pre_s;
#pragma unroll
        for (int i = 0; i < 16; i++) {
            float4 v = src[tid + 128 * i];
            dst[tid + 128 * i] = v;
            src[tid + 128 * i] = make_float4(0.f, 0.f, 0.f, 0.f);
        }
    }

    // Async-stage regressor weights r1, r2 (overlap with RNN loop)
    {
        const float4* s1 = (const float4*)r1_w;
#pragma unroll
        for (int i = 0; i < 32; i++)
            cp_async16(r1_s + 4 * (tid + 128 * i), s1 + tid + 128 * i);
        asm volatile("cp.async.commit_group;");
        const float4* s2 = (const float4*)r2_w;
#pragma unroll
        for (int i = 0; i < 32; i++)
            cp_async16(r2_s + 4 * (tid + 128 * i), s2 + tid + 128 * i);
        asm volatile("cp.async.commit_group;");
    }

    // Whole W_hh column in packed f32x2 regs
    ull wreg[64];
#pragma unroll
    for (int k = 0; k < 64; k++) {
        union { float2 f; ull u; } p;
        p.f.x = W_hh[(2 * k) * 128 + tid];
        p.f.y = W_hh[(2 * k + 1) * 128 + tid];
        wreg[k] = p.u;
    }
    __syncthreads();

    // step 0 (h_prev = 0)
    h2[tid] = tanh_fast(pre_s[tid]);
    float pre_n = pre_s[128 + tid];
    __syncthreads();

    int cb = 0;
#pragma unroll 1
    for (int step = 1; step < LQ_; step++) {
        float pre_n2 = (step + 1 < LQ_) ? pre_s[(step + 1) * 128 + tid] : 0.f;

        const ulonglong2* hp = (const ulonglong2*)(h2 + cb * 128);
        ull a0 = 0, a1 = 0, a2 = 0, a3 = 0;
#pragma unroll
        for (int k = 0; k < 32; k += 2) {
            ulonglong2 p0 = hp[k];
            ulonglong2 p1 = hp[k + 1];
            ffma2(a0, p0.x, wreg[2 * k]);
            ffma2(a1, p0.y, wreg[2 * k + 1]);
            ffma2(a2, p1.x, wreg[2 * k + 2]);
            ffma2(a3, p1.y, wreg[2 * k + 3]);
        }
        ull s01 = fadd2(fadd2(a0, a1), fadd2(a2, a3));
        float2 sv = unpack2(s01);
        float hn = tanh_fast(pre_n + sv.x + sv.y);
        h2[(cb ^ 1) * 128 + tid] = hn;
        cb ^= 1;
        pre_n = pre_n2;
        __syncthreads();
    }

    // Stage r3 into A (pre slab now dead)
    {
        const float4* s3 = (const float4*)r3_w;
#pragma unroll
        for (int i = 0; i < 32; i++)
            cp_async16(A + 4 * (tid + 128 * i), s3 + tid + 128 * i);
        asm volatile("cp.async.commit_group;");
    }

    asm volatile("cp.async.wait_group 2;" ::: "memory");
    __syncthreads();
    {
        const float* hin = h2 + cb * 128;
        float a0 = r1_b[tid], a1 = 0.f, a2 = 0.f, a3 = 0.f;
#pragma unroll 8
        for (int i = 0; i < 128; i += 4) {
            a0 = fmaf(hin[i],     r1_s[i * 128 + tid],       a0);
            a1 = fmaf(hin[i + 1], r1_s[(i + 1) * 128 + tid], a1);
            a2 = fmaf(hin[i + 2], r1_s[(i + 2) * 128 + tid], a2);
            a3 = fmaf(hin[i + 3], r1_s[(i + 3) * 128 + tid], a3);
        }
        v_s[tid] = (a0 + a1) + (a2 + a3);
    }
    asm volatile("cp.async.wait_group 1;" ::: "memory");
    __syncthreads();
    {
        float a0 = r2_b[tid], a1 = 0.f, a2 = 0.f, a3 = 0.f;
#pragma unroll 8
        for (int i = 0; i < 128; i += 4) {
            a0 = fmaf(v_s[i],     r2_s[i * 128 + tid],       a0);
            a1 = fmaf(v_s[i + 1], r2_s[(i + 1) * 128 + tid], a1);
            a2 = fmaf(v_s[i + 2], r2_s[(i + 2) * 128 + tid], a2);
            a3 = fmaf(v_s[i + 3], r2_s[(i + 3) * 128 + tid], a3);
        }
        h2[tid] = (a0 + a1) + (a2 + a3);
    }
    asm volatile("cp.async.wait_group 0;" ::: "memory");
    __syncthreads();
    {
        float a0 = r3_b[tid], a1 = 0.f, a2 = 0.f, a3 = 0.f;
#pragma unroll 8
        for (int i = 0; i < 128; i += 4) {
            a0 = fmaf(h2[i],     A[i * 128 + tid],       a0);
            a1 = fmaf(h2[i + 1], A[(i + 1) * 128 + tid], a1);
            a2 = fmaf(h2[i + 2], A[(i + 2) * 128 + tid], a2);
            a3 = fmaf(h2[i + 3], A[(i + 3) * 128 + tid], a3);
        }
        v_s[tid] = (a0 + a1) + (a2 + a3);
    }
    __syncthreads();

    // final 128 -> 8
    {
        const int w = tid >> 5, lane = tid & 31;
        float vo = v_s[tid];
        float p[8];
#pragma unroll
        for (int o = 0; o < 8; o++)
            p[o] = vo * r4_w[tid * 8 + o];
#pragma unroll
        for (int off = 16; off; off >>= 1)
#pragma unroll
            for (int o = 0; o < 8; o++)
                p[o] += __shfl_xor_sync(0xffffffffu, p[o], off);
        if (lane < 8) partf[w * 8 + lane] = p[lane];
    }
    __syncthreads();
    if (tid < 8)
        out[blockIdx.x * 8 + tid] = partf[tid] + partf[8 + tid] +
                                    partf[16 + tid] + partf[24 + tid] + r4_b[tid];
}

// ======================================================================
extern "C" void kernel_launch(void* const* d_in, const int* in_sizes, int n_in,
                              void* d_out, int out_size)
{
    const float* x     = (const float*)d_in[0];
    const float* times = (const float*)d_in[1];
    const float* mask  = (const float*)d_in[2];
    const float* query = (const float*)d_in[3];
    const float* w_lin = (const float*)d_in[4];
    const float* b_lin = (const float*)d_in[5];
    const float* w_per = (const float*)d_in[6];
    const float* b_per = (const float*)d_in[7];
    const float* Wq    = (const float*)d_in[8];
    const float* bq    = (const float*)d_in[9];
    const float* Wk    = (const float*)d_in[10];
    const float* bk    = (const float*)d_in[11];
    const float* Wo    = (const float*)d_in[12];
    const float* bo    = (const float*)d_in[13];
    const float* W_ih  = (const float*)d_in[14];
    const float* b_ih  = (const float*)d_in[15];
    const float* W_hh  = (const float*)d_in[16];
    const float* b_hh  = (const float*)d_in[17];
    const float* r1_w  = (const float*)d_in[18];
    const float* r1_b  = (const float*)d_in[19];
    const float* r2_w  = (const float*)d_in[20];
    const float* r2_b  = (const float*)d_in[21];
    const float* r3_w  = (const float*)d_in[22];
    const float* r3_b  = (const float*)d_in[23];
    const float* r4_w  = (const float*)d_in[24];
    const float* r4_b  = (const float*)d_in[25];
    float* out = (float*)d_out;

    const int S1_SMEM = (128 * SA_STR + 2 * CHUNK_ROWS * 128) * 4;  // 41984
    cudaFuncSetAttribute(stage1_kernel,
                         cudaFuncAttributeMaxDynamicSharedMemorySize, S1_SMEM);
    stage1_kernel<<<269, 256, S1_SMEM>>>(times, query, w_lin, b_lin, w_per, b_per,
                                         Wk, bk, Wq, bq, Wo, bo, W_ih, b_ih, b_hh);

    const int ATTN_SMEM = (512 + 4096 + 128 * 32 * 2) * 4;  // 51200
    cudaFuncSetAttribute(attn_kernel,
                         cudaFuncAttributeMaxDynamicSharedMemorySize, ATTN_SMEM);
    attn_kernel<<<dim3(4, 4, 16), 256, ATTN_SMEM>>>(x, mask);

    const int RNN_SMEM = (16384 * 3 + 256 + 128 + 32) * 4;  // 198272
    cudaFuncSetAttribute(rnn_regr_kernel,
                         cudaFuncAttributeMaxDynamicSharedMemorySize, RNN_SMEM);
    rnn_regr_kernel<<<16, 128, RNN_SMEM>>>(W_hh, r1_w, r1_b, r2_w, r2_b,
                                           r3_w, r3_b, r4_w, r4_b, out);
}

// round 17
// speedup vs baseline: 1.0435x; 1.0435x over previous
#include <cuda_runtime.h>
#include <cuda_bf16.h>
#include <math.h>

// Problem constants
#define B_   16
#define L_   256
#define LQ_  64
#define ET_  128
#define H_   4
#define ETK_ 32
#define DIM_ 64
#define D_IN_ 32
#define IE_  8

typedef unsigned long long ull;

// ---------------- scratch (device globals; no allocation) ----------------
__device__ float g_q[H_ * LQ_ * ETK_];   // (h, q, e)  pre-scaled by 1/sqrt(32)
__device__ float g_k[B_ * H_ * L_ * ETK_];
__device__ float g_Wc[ET_ * ET_];        // 128x128 compact Wo @ W_ih
__device__ float g_bc[ET_];
__device__ float g_pre[B_ * LQ_ * ET_];  // accumulated by attn (atomics); zeroed by rnn

__device__ __forceinline__ void ffma2(ull& acc, ull a, ull b)
{
    asm("fma.rn.f32x2 %0, %1, %2, %0;" : "+l"(acc) : "l"(a), "l"(b));
}
__device__ __forceinline__ ull fadd2(ull a, ull b)
{
    ull r; asm("add.rn.f32x2 %0, %1, %2;" : "=l"(r) : "l"(a), "l"(b)); return r;
}
__device__ __forceinline__ float2 unpack2(ull a)
{
    float2 v; asm("mov.b64 {%0,%1}, %2;" : "=f"(v.x), "=f"(v.y) : "l"(a)); return v;
}
__device__ __forceinline__ ull bcast2(float v)
{
    ull r; asm("mov.b64 %0, {%1,%1};" : "=l"(r) : "f"(v)); return r;
}
__device__ __forceinline__ float tanh_fast(float x)
{
    float r; asm("tanh.approx.f32 %0, %1;" : "=f"(r) : "f"(x)); return r;
}
__device__ __forceinline__ void cp_async16(float* dst_smem, const float4* src)
{
    unsigned d = (unsigned)__cvta_generic_to_shared(dst_smem);
    asm volatile("cp.async.cg.shared.global [%0], [%1], 16;" :: "r"(d), "l"(src));
}

// ======================================================================
// Kernel 1: 256 threads/block, 16 rows/block, f32x2 GEMM, transposed
// stride-18 s_a. W staged via cp.async DOUBLE-BUFFERED 32-row chunks.
// smem 41KB -> 5 blk/SM; 269 blocks = one wave.
//   blocks 0..255: K rows  256..259: Q  260..267: Wc  268: bias
// ======================================================================
#define SA_STR 18
#define CHUNK_ROWS 32
#define NCHUNK 4

__global__ void __launch_bounds__(256, 5)
stage1_kernel(
    const float* __restrict__ times, const float* __restrict__ query,
    const float* __restrict__ w_lin, const float* __restrict__ b_lin,
    const float* __restrict__ w_per, const float* __restrict__ b_per,
    const float* __restrict__ Wk, const float* __restrict__ bk,
    const float* __restrict__ Wq, const float* __restrict__ bq,
    const float* __restrict__ Wo, const float* __restrict__ bo,
    const float* __restrict__ W_ih, const float* __restrict__ b_ih,
    const float* __restrict__ b_hh)
{
    extern __shared__ float sm[];
    float* s_a = sm;                             // transposed [c][r], stride 18
    float* s_w0 = sm + 128 * SA_STR;             // 32 x 128 chunk buf 0
    float* s_w1 = s_w0 + CHUNK_ROWS * 128;       // 32 x 128 chunk buf 1
    __shared__ float tv[16];

    const int tid = threadIdx.x;
    const int bx  = blockIdx.x;
    const int tx = tid & 31;      // col group: cols 4*tx..4*tx+3
    const int ty = tid >> 5;      // row group: rows 2*ty, 2*ty+1

    if (bx < 268) {
        const bool is_wc = (bx >= 260);
        const bool is_q  = (!is_wc) && (bx >= 256);
        const float* W = is_wc ? W_ih : (is_q ? Wq : Wk);

        // prefetch chunk 0 immediately (overlaps s_a fill)
        {
            float* dst = s_w0;
#pragma unroll
            for (int i = 0; i < 4; i++)
                cp_async16(dst + 4 * (tid + 256 * i),
                           (const float4*)W + tid + 256 * i);
            asm volatile("cp.async.commit_group;");
        }

        // ---- fill s_a (transposed) ----
        if (!is_wc) {
            const int r0 = bx * 16;
            if (tid < 16) tv[tid] = is_q ? query[r0 - 4096 + tid] : times[r0 + tid];
            __syncthreads();
            const float wl = w_lin[0], bl = b_lin[0];
            for (int idx = tid; idx < 16 * 128; idx += 256) {
                int r = idx & 15, c = idx >> 4;
                float t = tv[r];
                s_a[c * SA_STR + r] =
                    (c == 0) ? fmaf(t, wl, bl)
                             : __sinf(fmaf(t, w_per[c - 1], b_per[c - 1]));
            }
        } else {
            const int cr0 = (bx - 260) * 16;
            for (int idx = tid; idx < 16 * 128; idx += 256) {
                int rr = idx & 15, c = idx >> 4;
                int cr = cr0 + rr;
                int r = (cr >> 5) * 64 + (cr & 31);   // d<32 rows of Wo
                s_a[c * SA_STR + rr] = Wo[r * 128 + c];
            }
        }

        // ---- f32x2 GEMM over 4 k-chunks, double-buffered cp.async ----
        ull acc01[2] = {0, 0};
        ull acc23[2] = {0, 0};
#pragma unroll
        for (int ch = 0; ch < NCHUNK; ch++) {
            float* buf_cur = (ch & 1) ? s_w1 : s_w0;
            if (ch + 1 < NCHUNK) {
                float* buf_nxt = (ch & 1) ? s_w0 : s_w1;
                const float4* src = (const float4*)(W + (ch + 1) * CHUNK_ROWS * 128);
#pragma unroll
                for (int i = 0; i < 4; i++)
                    cp_async16(buf_nxt + 4 * (tid + 256 * i), src + tid + 256 * i);
                asm volatile("cp.async.commit_group;");
                asm volatile("cp.async.wait_group 1;" ::: "memory");
            } else {
                asm volatile("cp.async.wait_group 0;" ::: "memory");
            }
            __syncthreads();

#pragma unroll 4
            for (int i = 0; i < CHUNK_ROWS; i++) {
                ulonglong2 wv = *(const ulonglong2*)(buf_cur + i * 128 + 4 * tx);
                float2 av = *(const float2*)(s_a + (ch * CHUNK_ROWS + i) * SA_STR + 2 * ty);
                ull e0 = bcast2(av.x), e1 = bcast2(av.y);
                ffma2(acc01[0], e0, wv.x); ffma2(acc23[0], e0, wv.y);
                ffma2(acc01[1], e1, wv.x); ffma2(acc23[1], e1, wv.y);
            }
            __syncthreads();   // all reads of buf_cur done before its overwrite
        }

        // ---- epilogue ----
        if (!is_wc) {
            const int r0 = bx * 16;
            const float* bias = is_q ? bq : bk;
            const float scale = is_q ? 0.17677669529663687f : 1.0f;
#pragma unroll
            for (int r = 0; r < 2; r++) {
                int grow = r0 + 2 * ty + r;
                float2 p01 = unpack2(acc01[r]);
                float2 p23 = unpack2(acc23[r]);
                float vr[4] = {p01.x, p01.y, p23.x, p23.y};
#pragma unroll
                for (int c = 0; c < 4; c++) {
                    int col = 4 * tx + c;
                    float v = (vr[c] + bias[col]) * scale;
                    int h = col >> 5, e = col & 31;
                    if (is_q) g_q[(h * LQ_ + (grow - 4096)) * ETK_ + e] = v;
                    else {
                        int b = grow >> 8, l = grow & 255;
                        g_k[((b * H_ + h) * L_ + l) * ETK_ + e] = v;
                    }
                }
            }
        } else {
            const int cr0 = (bx - 260) * 16;
#pragma unroll
            for (int r = 0; r < 2; r++) {
                float2 p01 = unpack2(acc01[r]);
                float2 p23 = unpack2(acc23[r]);
                int row = cr0 + 2 * ty + r;
                g_Wc[row * 128 + 4 * tx]     = p01.x;
                g_Wc[row * 128 + 4 * tx + 1] = p01.y;
                g_Wc[row * 128 + 4 * tx + 2] = p23.x;
                g_Wc[row * 128 + 4 * tx + 3] = p23.y;
            }
        }
    } else {
        // bias: bc = (bo + sum_ones Wo[r]) @ W_ih + b_ih + b_hh
        const int j = tid & 127, hf = tid >> 7;
        float accv = 0.f;
#pragma unroll 4
        for (int i = 0; i < 64; i++) {
            int oi = hf * 64 + i;
            int r = (oi >> 5) * 64 + 32 + (oi & 31);  // "ones" rows of Wo
            accv += Wo[r * 128 + j];
        }
        s_a[256 + hf * 128 + j] = accv;
        __syncthreads();
        if (tid < 128) s_a[tid] = bo[tid] + s_a[256 + tid] + s_a[384 + tid];

        float acc = (tid < 128) ? (b_ih[tid] + b_hh[tid]) : 0.f;
#pragma unroll
        for (int ch = 0; ch < 2; ch++) {
            __syncthreads();
#pragma unroll
            for (int idx = tid * 4; idx < 64 * 128; idx += 1024)
                *(float4*)(s_w0 + idx) = *(const float4*)(W_ih + ch * 64 * 128 + idx);
            __syncthreads();
            if (tid < 128) {
#pragma unroll 8
                for (int i = 0; i < 64; i++)
                    acc = fmaf(s_a[ch * 64 + i], s_w0[i * 128 + tid], acc);
            }
        }
        if (tid < 128) g_bc[tid] = acc;
    }
}

// ======================================================================
// Kernel 2: masked attention + fused partial-pre accumulation.
// grid (qt=4, h=4, b=16), 256 threads, smem 51200 B -> 4 blocks/SM.
// ======================================================================
__global__ void __launch_bounds__(256, 4)
attn_kernel(const float* __restrict__ x, const float* __restrict__ mask)
{
    extern __shared__ float smem[];
    float*  qv  = smem;                          // 512 (reused as att_s later)
    float*  s_s = smem + 512;                    // 16*256
    float2* mxm = (float2*)(smem + 512 + 4096);  // 128*32 float2 (32KB chunk)

    const int tid = threadIdx.x;
    const int qt = blockIdx.x, h = blockIdx.y, b = blockIdx.z;

    qv[tid]       = g_q[(h * LQ_ + qt * 16) * ETK_ + tid];
    qv[tid + 256] = g_q[(h * LQ_ + qt * 16) * ETK_ + tid + 256];
    __syncthreads();

    // scores: thread = key k, all 16 queries
    {
        const int k = tid;
        const float* kp = g_k + ((b * H_ + h) * L_ + k) * ETK_;
        float kv[32];
#pragma unroll
        for (int i = 0; i < 8; i++) {
            float4 v = *(const float4*)(kp + 4 * i);
            kv[4*i] = v.x; kv[4*i+1] = v.y; kv[4*i+2] = v.z; kv[4*i+3] = v.w;
        }
#pragma unroll
        for (int q = 0; q < 16; q++) {
            float acc = 0.f;
#pragma unroll
            for (int e = 0; e < 32; e++) acc = fmaf(qv[q * 32 + e], kv[e], acc);
            s_s[q * 256 + k] = acc;
        }
    }
    __syncthreads();

    // row max + exp (8 warps x 2 queries)
    {
        const int wq = tid >> 5, lane = tid & 31;
#pragma unroll
        for (int qq = 0; qq < 2; qq++) {
            int q = wq * 2 + qq;
            float vals[8], m = -1e30f;
#pragma unroll
            for (int i = 0; i < 8; i++) {
                vals[i] = s_s[q * 256 + lane + 32 * i];
                m = fmaxf(m, vals[i]);
            }
#pragma unroll
            for (int off = 16; off; off >>= 1)
                m = fmaxf(m, __shfl_xor_sync(0xffffffffu, m, off));
#pragma unroll
            for (int i = 0; i < 8; i++)
                s_s[q * 256 + lane + 32 * i] = __expf(vals[i] - m);
        }
    }

    // num/den over 2 key-chunks; thread = (q = tid>>4, d-pair = tid&15)
    const int q  = tid >> 4;
    const int d0 = (tid & 15) * 2;
    float n0 = 0.f, de0 = 0.f, n1 = 0.f, de1 = 0.f;
#pragma unroll
    for (int ch = 0; ch < 2; ch++) {
        __syncthreads();   // protect mxm reuse
        const float* xb = x    + (b * L_ + ch * 128) * D_IN_;
        const float* mb = mask + (b * L_ + ch * 128) * D_IN_;
        for (int idx = tid; idx < 128 * D_IN_; idx += 256) {
            float m = mb[idx];
            mxm[idx] = make_float2(m * xb[idx], m);
        }
        __syncthreads();

        const float* ep = s_s + q * 256 + ch * 128;
#pragma unroll 4
        for (int k = 0; k < 128; k++) {
            float e = ep[k];
            float4 v = *(const float4*)(mxm + k * 32 + d0);
            n0 = fmaf(e, v.x, n0); de0 = fmaf(e, v.y, de0);
            n1 = fmaf(e, v.z, n1); de1 = fmaf(e, v.w, de1);
        }
    }
    __syncthreads();
    qv[q * 32 + d0]     = (de0 > 0.f) ? (n0 / de0) : 0.f;   // att_s
    qv[q * 32 + d0 + 1] = (de1 > 0.f) ? (n1 / de1) : 0.f;
    __syncthreads();

    // partial pre: pre[b, q, col] += sum_d att[q,d] * Wc[h*32+d, col]
    {
        const int col = tid & 127;
        const int rh  = (tid >> 7) * 8;    // rows rh..rh+7
        const float* wp = g_Wc + (h * 32) * 128 + col;
        float a[8];
#pragma unroll
        for (int r = 0; r < 8; r++) a[r] = 0.f;
#pragma unroll 4
        for (int d = 0; d < 32; d++) {
            float w = wp[d * 128];
#pragma unroll
            for (int r = 0; r < 8; r++)
                a[r] = fmaf(qv[(rh + r) * 32 + d], w, a[r]);
        }
        float bias = (h == 0) ? g_bc[col] : 0.f;
        float* pp = g_pre + (b * LQ_ + qt * 16 + rh) * 128 + col;
#pragma unroll
        for (int r = 0; r < 8; r++)
            atomicAdd(pp + r * 128, a[r] + bias);
    }
}

// ======================================================================
// Kernel 3: RNN + regressor. grid 16 x 128 threads. Regressor matvecs
// use 4 accumulators.
// ======================================================================
__global__ void __launch_bounds__(128, 1)
rnn_regr_kernel(const float* __restrict__ W_hh,
                const float* __restrict__ r1_w, const float* __restrict__ r1_b,
                const float* __restrict__ r2_w, const float* __restrict__ r2_b,
                const float* __restrict__ r3_w, const float* __restrict__ r3_b,
                const float* __restrict__ r4_w, const float* __restrict__ r4_b,
                float* __restrict__ out)
{
    extern __shared__ float smem[];
    float* A     = smem;             // 16384 floats: pre slab (8192) then r3_w
    float* r1_s  = smem + 16384;     // 16384
    float* r2_s  = r1_s + 16384;     // 16384
    float* h2    = r2_s + 16384;     // 256
    float* v_s   = h2 + 256;         // 128
    float* partf = v_s + 128;        // 32
    float* pre_s = A;

    const int tid = threadIdx.x;

    // Stage pre slab and zero g_pre for next replay
    {
        float4* src = (float4*)(g_pre + blockIdx.x * LQ_ * ET_);
        float4* dst = (float4*)pre_s;
#pragma unroll
        for (int i = 0; i < 16; i++) {
            float4 v = src[tid + 128 * i];
            dst[tid + 128 * i] = v;
            src[tid + 128 * i] = make_float4(0.f, 0.f, 0.f, 0.f);
        }
    }

    // Async-stage regressor weights r1, r2 (overlap with RNN loop)
    {
        const float4* s1 = (const float4*)r1_w;
#pragma unroll
        for (int i = 0; i < 32; i++)
            cp_async16(r1_s + 4 * (tid + 128 * i), s1 + tid + 128 * i);
        asm volatile("cp.async.commit_group;");
        const float4* s2 = (const float4*)r2_w;
#pragma unroll
        for (int i = 0; i < 32; i++)
            cp_async16(r2_s + 4 * (tid + 128 * i), s2 + tid + 128 * i);
        asm volatile("cp.async.commit_group;");
    }

    // Whole W_hh column in packed f32x2 regs
    ull wreg[64];
#pragma unroll
    for (int k = 0; k < 64; k++) {
        union { float2 f; ull u; } p;
        p.f.x = W_hh[(2 * k) * 128 + tid];
        p.f.y = W_hh[(2 * k + 1) * 128 + tid];
        wreg[k] = p.u;
    }
    __syncthreads();

    // step 0 (h_prev = 0)
    h2[tid] = tanh_fast(pre_s[tid]);
    float pre_n = pre_s[128 + tid];
    __syncthreads();

    int cb = 0;
#pragma unroll 1
    for (int step = 1; step < LQ_; step++) {
        float pre_n2 = (step + 1 < LQ_) ? pre_s[(step + 1) * 128 + tid] : 0.f;

        const ulonglong2* hp = (const ulonglong2*)(h2 + cb * 128);
        ull a0 = 0, a1 = 0, a2 = 0, a3 = 0;
#pragma unroll
        for (int k = 0; k < 32; k += 2) {
            ulonglong2 p0 = hp[k];
            ulonglong2 p1 = hp[k + 1];
            ffma2(a0, p0.x, wreg[2 * k]);
            ffma2(a1, p0.y, wreg[2 * k + 1]);
            ffma2(a2, p1.x, wreg[2 * k + 2]);
            ffma2(a3, p1.y, wreg[2 * k + 3]);
        }
        ull s01 = fadd2(fadd2(a0, a1), fadd2(a2, a3));
        float2 sv = unpack2(s01);
        float hn = tanh_fast(pre_n + sv.x + sv.y);
        h2[(cb ^ 1) * 128 + tid] = hn;
        cb ^= 1;
        pre_n = pre_n2;
        __syncthreads();
    }

    // Stage r3 into A (pre slab now dead)
    {
        const float4* s3 = (const float4*)r3_w;
#pragma unroll
        for (int i = 0; i < 32; i++)
            cp_async16(A + 4 * (tid + 128 * i), s3 + tid + 128 * i);
        asm volatile("cp.async.commit_group;");
    }

    asm volatile("cp.async.wait_group 2;" ::: "memory");
    __syncthreads();
    {
        const float* hin = h2 + cb * 128;
        float a0 = r1_b[tid], a1 = 0.f, a2 = 0.f, a3 = 0.f;
#pragma unroll 8
        for (int i = 0; i < 128; i += 4) {
            a0 = fmaf(hin[i],     r1_s[i * 128 + tid],       a0);
            a1 = fmaf(hin[i + 1], r1_s[(i + 1) * 128 + tid], a1);
            a2 = fmaf(hin[i + 2], r1_s[(i + 2) * 128 + tid], a2);
            a3 = fmaf(hin[i + 3], r1_s[(i + 3) * 128 + tid], a3);
        }
        v_s[tid] = (a0 + a1) + (a2 + a3);
    }
    asm volatile("cp.async.wait_group 1;" ::: "memory");
    __syncthreads();
    {
        float a0 = r2_b[tid], a1 = 0.f, a2 = 0.f, a3 = 0.f;
#pragma unroll 8
        for (int i = 0; i < 128; i += 4) {
            a0 = fmaf(v_s[i],     r2_s[i * 128 + tid],       a0);
            a1 = fmaf(v_s[i + 1], r2_s[(i + 1) * 128 + tid], a1);
            a2 = fmaf(v_s[i + 2], r2_s[(i + 2) * 128 + tid], a2);
            a3 = fmaf(v_s[i + 3], r2_s[(i + 3) * 128 + tid], a3);
        }
        h2[tid] = (a0 + a1) + (a2 + a3);
    }
    asm volatile("cp.async.wait_group 0;" ::: "memory");
    __syncthreads();
    {
        float a0 = r3_b[tid], a1 = 0.f, a2 = 0.f, a3 = 0.f;
#pragma unroll 8
        for (int i = 0; i < 128; i += 4) {
            a0 = fmaf(h2[i],     A[i * 128 + tid],       a0);
            a1 = fmaf(h2[i + 1], A[(i + 1) * 128 + tid], a1);
            a2 = fmaf(h2[i + 2], A[(i + 2) * 128 + tid], a2);
            a3 = fmaf(h2[i + 3], A[(i + 3) * 128 + tid], a3);
        }
        v_s[tid] = (a0 + a1) + (a2 + a3);
    }
    __syncthreads();

    // final 128 -> 8
    {
        const int w = tid >> 5, lane = tid & 31;
        float vo = v_s[tid];
        float p[8];
#pragma unroll
        for (int o = 0; o < 8; o++)
            p[o] = vo * r4_w[tid * 8 + o];
#pragma unroll
        for (int off = 16; off; off >>= 1)
#pragma unroll
            for (int o = 0; o < 8; o++)
                p[o] += __shfl_xor_sync(0xffffffffu, p[o], off);
        if (lane < 8) partf[w * 8 + lane] = p[lane];
    }
    __syncthreads();
    if (tid < 8)
        out[blockIdx.x * 8 + tid] = partf[tid] + partf[8 + tid] +
                                    partf[16 + tid] + partf[24 + tid] + r4_b[tid];
}

// ======================================================================
extern "C" void kernel_launch(void* const* d_in, const int* in_sizes, int n_in,
                              void* d_out, int out_size)
{
    const float* x     = (const float*)d_in[0];
    const float* times = (const float*)d_in[1];
    const float* mask  = (const float*)d_in[2];
    const float* query = (const float*)d_in[3];
    const float* w_lin = (const float*)d_in[4];
    const float* b_lin = (const float*)d_in[5];
    const float* w_per = (const float*)d_in[6];
    const float* b_per = (const float*)d_in[7];
    const float* Wq    = (const float*)d_in[8];
    const float* bq    = (const float*)d_in[9];
    const float* Wk    = (const float*)d_in[10];
    const float* bk    = (const float*)d_in[11];
    const float* Wo    = (const float*)d_in[12];
    const float* bo    = (const float*)d_in[13];
    const float* W_ih  = (const float*)d_in[14];
    const float* b_ih  = (const float*)d_in[15];
    const float* W_hh  = (const float*)d_in[16];
    const float* b_hh  = (const float*)d_in[17];
    const float* r1_w  = (const float*)d_in[18];
    const float* r1_b  = (const float*)d_in[19];
    const float* r2_w  = (const float*)d_in[20];
    const float* r2_b  = (const float*)d_in[21];
    const float* r3_w  = (const float*)d_in[22];
    const float* r3_b  = (const float*)d_in[23];
    const float* r4_w  = (const float*)d_in[24];
    const float* r4_b  = (const float*)d_in[25];
    float* out = (float*)d_out;

    const int S1_SMEM = (128 * SA_STR + 2 * CHUNK_ROWS * 128) * 4;  // 41984
    cudaFuncSetAttribute(stage1_kernel,
                         cudaFuncAttributeMaxDynamicSharedMemorySize, S1_SMEM);
    stage1_kernel<<<269, 256, S1_SMEM>>>(times, query, w_lin, b_lin, w_per, b_per,
                                         Wk, bk, Wq, bq, Wo, bo, W_ih, b_ih, b_hh);

    const int ATTN_SMEM = (512 + 4096 + 128 * 32 * 2) * 4;  // 51200
    cudaFuncSetAttribute(attn_kernel,
                         cudaFuncAttributeMaxDynamicSharedMemorySize, ATTN_SMEM);
    attn_kernel<<<dim3(4, 4, 16), 256, ATTN_SMEM>>>(x, mask);

    const int RNN_SMEM = (16384 * 3 + 256 + 128 + 32) * 4;  // 198272
    cudaFuncSetAttribute(rnn_regr_kernel,
                         cudaFuncAttributeMaxDynamicSharedMemorySize, RNN_SMEM);
    rnn_regr_kernel<<<16, 128, RNN_SMEM>>>(W_hh, r1_w, r1_b, r2_w, r2_b,
                                           r3_w, r3_b, r4_w, r4_b, out);
}